// round 7
// baseline (speedup 1.0000x reference)
#include <cuda_runtime.h>

#define XD 38
#define YD 24
#define ZD 24
#define RV (XD*YD*ZD)          // 21888
#define BB 16
#define CC 64
#define NN 16384
#define TOTVOX (BB*RV)         // 350208 (= 5472*64)
#define NPTS   (BB*NN)         // 262144
#define FIN_BLOCKS (TOTVOX/64)      // 5472
#define GROUPS_PER_BATCH (RV/64)    // 342

// scratch (__device__ globals; zero-initialized at load; self-cleaned every launch)
__device__ __align__(16) int   g_cnt[TOTVOX];                  // per-voxel count
__device__ __align__(16) float g_stage[(size_t)TOTVOX * CC];   // [B, R, C] accumulator (~90MB)

// vectorized global float reduction
__device__ __forceinline__ void red_add_v4(float* addr, float a, float b, float c, float d) {
    asm volatile("red.global.add.v4.f32 [%0], {%1, %2, %3, %4};"
                 :: "l"(addr), "f"(a), "f"(b), "f"(c), "f"(d) : "memory");
}

// ---------------- scatter (fused index): feat [B,C,N] -> red.v4 into g_stage [B,R,C] --
// grid (NN/32, BB), 256 threads. Threads 0-31 compute voxel ids for the 32 points.
__global__ __launch_bounds__(256)
void scatter_k(const float* __restrict__ feat, const float* __restrict__ coords) {
    __shared__ float sm[64][33];
    __shared__ int   s_flat[32];
    int b  = blockIdx.y;
    int p0 = blockIdx.x * 32;
    int t  = threadIdx.x;

    if (t < 32) {
        const float* cp = coords + ((size_t)b * NN + p0 + t) * 3;
        float cx = cp[0], cy = cp[1], cz = cp[2];
        int ix = (int)floorf(cx / 0.3f) + 19;
        int iy = (int)floorf(cy / 0.3f) + 12;
        int iz = (int)floorf(cz / 0.2f) + 12;
        bool valid = (ix >= 0) & (ix < XD) & (iy >= 0) & (iy < YD) & (iz >= 0) & (iz < ZD);
        int flat = -1;
        if (valid) {
            flat = ix * (YD*ZD) + iy * ZD + iz;
            atomicAdd(&g_cnt[b*RV + flat], 1);
        }
        s_flat[t] = flat;
    }

    int j  = t & 31;
    int rb = t >> 5;
    const float* fb = feat + (size_t)b * CC * NN + p0 + j;
    #pragma unroll
    for (int k = 0; k < 8; k++) {
        int row = rb + k * 8;
        sm[row][j] = fb[(size_t)row * NN];
    }
    __syncthreads();

    int jp = t >> 3;                  // point in tile 0..31
    int q  = t & 7;                   // channel octet 0..7
    int flat = s_flat[jp];
    if (flat >= 0) {
        float* dst = g_stage + ((size_t)(b * RV + flat) * CC) + q * 8;
        int c0 = q * 8;
        red_add_v4(dst,     sm[c0+0][jp], sm[c0+1][jp], sm[c0+2][jp], sm[c0+3][jp]);
        red_add_v4(dst + 4, sm[c0+4][jp], sm[c0+5][jp], sm[c0+6][jp], sm[c0+7][jp]);
    }
}

// ---------------- finalize: staging -> averaged, transposed output; self-clean -------
__global__ __launch_bounds__(256)
void finalize_k(float* __restrict__ out) {
    __shared__ float sm[64 * 65];     // [channel][voxel]
    __shared__ float s_inv[64];
    __shared__ int   s_cnt[64];
    int t = threadIdx.x;
    int gvbase = blockIdx.x * 64;

    if (t < 64) {
        int c = g_cnt[gvbase + t];    // read, THEN clean (same thread -> ordered)
        s_cnt[t] = c;
        s_inv[t] = 1.f / (float)max(c, 1);
        g_cnt[gvbase + t] = 0;        // self-clean, race-free
    }
    __syncthreads();

    float4* stg4 = reinterpret_cast<float4*>(g_stage + (size_t)gvbase * CC);  // 1024 float4
    #pragma unroll
    for (int k = 0; k < 4; k++) {
        int i   = t + 256 * k;        // float4 index within block
        int vox = i >> 4;
        int c4  = i & 15;
        bool occ = (s_cnt[vox] > 0);
        float4 v = make_float4(0.f, 0.f, 0.f, 0.f);
        if (occ) v = stg4[i];         // empty voxels: rows known zero, skip the read
        float inv = s_inv[vox];
        int c0 = c4 * 4;
        sm[(c0+0) * 65 + vox] = v.x * inv;
        sm[(c0+1) * 65 + vox] = v.y * inv;
        sm[(c0+2) * 65 + vox] = v.z * inv;
        sm[(c0+3) * 65 + vox] = v.w * inv;
        if (occ) stg4[i] = make_float4(0.f, 0.f, 0.f, 0.f);   // self-clean
    }
    __syncthreads();

    int b  = blockIdx.x / GROUPS_PER_BATCH;
    int vb = (blockIdx.x % GROUPS_PER_BATCH) * 64;
    int c  = t >> 2;                  // 0..63
    int q  = t & 3;                   // 0..3 -> 16 voxels each
    float* ob = out + ((size_t)(b * CC + c)) * RV + vb + q * 16;
    const float* sp = &sm[c * 65 + q * 16];
    #pragma unroll
    for (int k = 0; k < 4; k++) {
        *reinterpret_cast<float4*>(ob + k*4) =
            make_float4(sp[k*4+0], sp[k*4+1], sp[k*4+2], sp[k*4+3]);
    }
}

extern "C" void kernel_launch(void* const* d_in, const int* in_sizes, int n_in,
                              void* d_out, int out_size) {
    const float* feat   = (const float*)d_in[0];   // [B, C, N]
    const float* coords = (const float*)d_in[1];   // [B, N, 3]
    float* out = (float*)d_out;                    // [B, C, X, Y, Z]

    scatter_k<<<dim3(NN / 32, BB), 256>>>(feat, coords);   // 8192 blocks
    finalize_k<<<FIN_BLOCKS, 256>>>(out);                  // 5472 blocks
}

// round 8
// speedup vs baseline: 1.6310x; 1.6310x over previous
#include <cuda_runtime.h>

#define XD 38
#define YD 24
#define ZD 24
#define RV (XD*YD*ZD)          // 21888
#define BB 16
#define CC 64
#define NN 16384
#define TOTVOX (BB*RV)         // 350208 (= 5472*64)
#define FIN_BLOCKS (TOTVOX/64)      // 5472
#define GROUPS_PER_BATCH (RV/64)    // 342

// scratch (__device__ globals; zero-initialized at load; self-cleaned every launch)
__device__ __align__(16) int   g_cnt[TOTVOX];                  // per-voxel count
__device__ __align__(16) float g_stage[(size_t)TOTVOX * CC];   // [B, R, C] accumulator (~90MB)

// vectorized global float reduction
__device__ __forceinline__ void red_add_v4(float* addr, float a, float b, float c, float d) {
    asm volatile("red.global.add.v4.f32 [%0], {%1, %2, %3, %4};"
                 :: "l"(addr), "f"(a), "f"(b), "f"(c), "f"(d) : "memory");
}

// ---------------- scatter (fused index): feat [B,C,N] -> red.v4 into g_stage [B,R,C] --
// grid (NN/32, BB), 256 threads. Threads 0-31 compute voxel ids for the 32 points.
__global__ __launch_bounds__(256)
void scatter_k(const float* __restrict__ feat, const float* __restrict__ coords) {
    __shared__ float sm[64][33];
    __shared__ int   s_flat[32];
    int b  = blockIdx.y;
    int p0 = blockIdx.x * 32;
    int t  = threadIdx.x;

    if (t < 32) {
        const float* cp = coords + ((size_t)b * NN + p0 + t) * 3;
        float cx = cp[0], cy = cp[1], cz = cp[2];
        int ix = (int)floorf(cx / 0.3f) + 19;
        int iy = (int)floorf(cy / 0.3f) + 12;
        int iz = (int)floorf(cz / 0.2f) + 12;
        bool valid = (ix >= 0) & (ix < XD) & (iy >= 0) & (iy < YD) & (iz >= 0) & (iz < ZD);
        int flat = -1;
        if (valid) {
            flat = ix * (YD*ZD) + iy * ZD + iz;
            atomicAdd(&g_cnt[b*RV + flat], 1);
        }
        s_flat[t] = flat;
    }

    int j  = t & 31;
    int rb = t >> 5;
    const float* fb = feat + (size_t)b * CC * NN + p0 + j;
    #pragma unroll
    for (int k = 0; k < 8; k++) {
        int row = rb + k * 8;
        sm[row][j] = fb[(size_t)row * NN];
    }
    __syncthreads();

    int jp = t >> 3;                  // point in tile 0..31
    int q  = t & 7;                   // channel octet 0..7
    int flat = s_flat[jp];
    if (flat >= 0) {
        float* dst = g_stage + ((size_t)(b * RV + flat) * CC) + q * 8;
        int c0 = q * 8;
        red_add_v4(dst,     sm[c0+0][jp], sm[c0+1][jp], sm[c0+2][jp], sm[c0+3][jp]);
        red_add_v4(dst + 4, sm[c0+4][jp], sm[c0+5][jp], sm[c0+6][jp], sm[c0+7][jp]);
    }
}

// ---------------- finalize: staging -> averaged, transposed output; self-clean -------
// R6 form: UNCONDITIONAL staging reads (ptxas batches 4x LDG.128, MLP=4).
__global__ __launch_bounds__(256)
void finalize_k(float* __restrict__ out) {
    __shared__ float sm[64 * 65];     // [channel][voxel]
    __shared__ float s_inv[64];
    __shared__ int   s_cnt[64];
    int t = threadIdx.x;
    int gvbase = blockIdx.x * 64;

    if (t < 64) {
        int c = g_cnt[gvbase + t];    // read, THEN clean (same thread -> ordered)
        s_cnt[t] = c;
        s_inv[t] = 1.f / (float)max(c, 1);
        g_cnt[gvbase + t] = 0;        // self-clean, race-free
    }
    __syncthreads();

    float4* stg4 = reinterpret_cast<float4*>(g_stage + (size_t)gvbase * CC);  // 1024 float4
    #pragma unroll
    for (int k = 0; k < 4; k++) {
        int i   = t + 256 * k;        // float4 index within block
        int vox = i >> 4;
        int c4  = i & 15;
        float4 v = stg4[i];           // unconditional -> front-batched, MLP=4
        float inv = s_inv[vox];
        int c0 = c4 * 4;
        sm[(c0+0) * 65 + vox] = v.x * inv;
        sm[(c0+1) * 65 + vox] = v.y * inv;
        sm[(c0+2) * 65 + vox] = v.z * inv;
        sm[(c0+3) * 65 + vox] = v.w * inv;
        if (s_cnt[vox] > 0) stg4[i] = make_float4(0.f, 0.f, 0.f, 0.f);  // self-clean
    }
    __syncthreads();

    int b  = blockIdx.x / GROUPS_PER_BATCH;
    int vb = (blockIdx.x % GROUPS_PER_BATCH) * 64;
    int c  = t >> 2;                  // 0..63
    int q  = t & 3;                   // 0..3 -> 16 voxels each
    float* ob = out + ((size_t)(b * CC + c)) * RV + vb + q * 16;
    const float* sp = &sm[c * 65 + q * 16];
    #pragma unroll
    for (int k = 0; k < 4; k++) {
        *reinterpret_cast<float4*>(ob + k*4) =
            make_float4(sp[k*4+0], sp[k*4+1], sp[k*4+2], sp[k*4+3]);
    }
}

extern "C" void kernel_launch(void* const* d_in, const int* in_sizes, int n_in,
                              void* d_out, int out_size) {
    const float* feat   = (const float*)d_in[0];   // [B, C, N]
    const float* coords = (const float*)d_in[1];   // [B, N, 3]
    float* out = (float*)d_out;                    // [B, C, X, Y, Z]

    scatter_k<<<dim3(NN / 32, BB), 256>>>(feat, coords);   // 8192 blocks
    finalize_k<<<FIN_BLOCKS, 256>>>(out);                  // 5472 blocks
}

// round 9
// speedup vs baseline: 1.6854x; 1.0334x over previous
#include <cuda_runtime.h>

#define XD 38
#define YD 24
#define ZD 24
#define RV (XD*YD*ZD)          // 21888
#define BB 16
#define CC 64
#define NN 16384
#define TOTVOX (BB*RV)         // 350208 (= 5472*64)
#define NPTS   (BB*NN)         // 262144
#define FIN_BLOCKS (TOTVOX/64)      // 5472
#define GROUPS_PER_BATCH (RV/64)    // 342

// scratch (__device__ globals; zero-initialized at load; self-cleaned every launch)
__device__ __align__(16) int   g_cnt[TOTVOX];                  // per-voxel count
__device__ __align__(16) float g_stage[(size_t)TOTVOX * CC];   // [B, R, C] accumulator (~90MB)

__device__ __forceinline__ void red_add_v4(float* addr, float a, float b, float c, float d) {
    asm volatile("red.global.add.v4.f32 [%0], {%1, %2, %3, %4};"
                 :: "l"(addr), "f"(a), "f"(b), "f"(c), "f"(d) : "memory");
}

__device__ __forceinline__ int coord_to_flat(float cx, float cy, float cz) {
    int ix = (int)floorf(cx / 0.3f) + 19;
    int iy = (int)floorf(cy / 0.3f) + 12;
    int iz = (int)floorf(cz / 0.2f) + 12;
    bool valid = (ix >= 0) & (ix < XD) & (iy >= 0) & (iy < YD) & (iz >= 0) & (iz < ZD);
    return valid ? (ix * (YD*ZD) + iy * ZD + iz) : -1;
}

// ---------------- index: per-voxel counts only ----------------
__global__ __launch_bounds__(256)
void index_k(const float* __restrict__ coords) {
    int i = blockIdx.x * blockDim.x + threadIdx.x;    // point id
    if (i >= NPTS) return;
    float cx = coords[3*i + 0];
    float cy = coords[3*i + 1];
    float cz = coords[3*i + 2];
    int flat = coord_to_flat(cx, cy, cz);
    if (flat >= 0) atomicAdd(&g_cnt[(i >> 14) * RV + flat], 1);   // i>>14 = batch
}

// ---------------- scatter: singleton voxels use STG, shared voxels use RED ----------
// grid (NN/32, BB), 256 threads. Threads 0-31 compute voxel ids + count lookup.
__global__ __launch_bounds__(256)
void scatter_k(const float* __restrict__ feat, const float* __restrict__ coords) {
    __shared__ float sm[64][33];
    __shared__ int   s_flat[32];      // flat id, or flat|SINGLE_BIT
    int b  = blockIdx.y;
    int p0 = blockIdx.x * 32;
    int t  = threadIdx.x;

    if (t < 32) {
        const float* cp = coords + ((size_t)b * NN + p0 + t) * 3;
        int flat = coord_to_flat(cp[0], cp[1], cp[2]);
        int tag = flat;
        if (flat >= 0) {
            int cnt = g_cnt[b*RV + flat];
            if (cnt == 1) tag = flat | 0x40000000;    // singleton marker
        }
        s_flat[t] = tag;
    }

    int j  = t & 31;
    int rb = t >> 5;
    const float* fb = feat + (size_t)b * CC * NN + p0 + j;
    #pragma unroll
    for (int k = 0; k < 8; k++) {
        int row = rb + k * 8;
        sm[row][j] = fb[(size_t)row * NN];
    }
    __syncthreads();

    int jp = t >> 3;                  // point in tile 0..31
    int q  = t & 7;                   // channel octet 0..7
    int tag = s_flat[jp];
    if (tag >= 0) {
        bool single = (tag & 0x40000000) != 0;
        int flat = tag & 0x3FFFFFFF;
        float* dst = g_stage + ((size_t)(b * RV + flat) * CC) + q * 8;
        int c0 = q * 8;
        float4 x = make_float4(sm[c0+0][jp], sm[c0+1][jp], sm[c0+2][jp], sm[c0+3][jp]);
        float4 y = make_float4(sm[c0+4][jp], sm[c0+5][jp], sm[c0+6][jp], sm[c0+7][jp]);
        if (single) {                 // sole writer of this row: plain stores
            *reinterpret_cast<float4*>(dst)     = x;
            *reinterpret_cast<float4*>(dst + 4) = y;
        } else {                      // shared row: atomic reduction
            red_add_v4(dst,     x.x, x.y, x.z, x.w);
            red_add_v4(dst + 4, y.x, y.y, y.z, y.w);
        }
    }
}

// ---------------- finalize: staging -> averaged, transposed output; self-clean -------
__global__ __launch_bounds__(256)
void finalize_k(float* __restrict__ out) {
    __shared__ float sm[64 * 65];     // [channel][voxel]
    __shared__ float s_inv[64];
    __shared__ int   s_cnt[64];
    int t = threadIdx.x;
    int gvbase = blockIdx.x * 64;

    if (t < 64) {
        int c = g_cnt[gvbase + t];    // read, THEN clean (same thread -> ordered)
        s_cnt[t] = c;
        s_inv[t] = 1.f / (float)max(c, 1);
        g_cnt[gvbase + t] = 0;        // self-clean counts
    }
    __syncthreads();

    float4* stg4 = reinterpret_cast<float4*>(g_stage + (size_t)gvbase * CC);  // 1024 float4
    #pragma unroll
    for (int k = 0; k < 4; k++) {
        int i   = t + 256 * k;        // float4 index within block
        int vox = i >> 4;
        int c4  = i & 15;
        float4 v = stg4[i];           // unconditional -> front-batched, MLP=4
        float inv = s_inv[vox];
        int c0 = c4 * 4;
        sm[(c0+0) * 65 + vox] = v.x * inv;
        sm[(c0+1) * 65 + vox] = v.y * inv;
        sm[(c0+2) * 65 + vox] = v.z * inv;
        sm[(c0+3) * 65 + vox] = v.w * inv;
        // only RED-accumulated rows (cnt>=2) need zeroing; cnt==1 rows are
        // fully overwritten by STG each launch, cnt==0 rows never written
        if (s_cnt[vox] > 1) stg4[i] = make_float4(0.f, 0.f, 0.f, 0.f);
    }
    __syncthreads();

    int b  = blockIdx.x / GROUPS_PER_BATCH;
    int vb = (blockIdx.x % GROUPS_PER_BATCH) * 64;
    int c  = t >> 2;                  // 0..63
    int q  = t & 3;                   // 0..3 -> 16 voxels each
    float* ob = out + ((size_t)(b * CC + c)) * RV + vb + q * 16;
    const float* sp = &sm[c * 65 + q * 16];
    #pragma unroll
    for (int k = 0; k < 4; k++) {
        *reinterpret_cast<float4*>(ob + k*4) =
            make_float4(sp[k*4+0], sp[k*4+1], sp[k*4+2], sp[k*4+3]);
    }
}

extern "C" void kernel_launch(void* const* d_in, const int* in_sizes, int n_in,
                              void* d_out, int out_size) {
    const float* feat   = (const float*)d_in[0];   // [B, C, N]
    const float* coords = (const float*)d_in[1];   // [B, N, 3]
    float* out = (float*)d_out;                    // [B, C, X, Y, Z]

    index_k<<<NPTS / 256, 256>>>(coords);                  // 1024 blocks
    scatter_k<<<dim3(NN / 32, BB), 256>>>(feat, coords);   // 8192 blocks
    finalize_k<<<FIN_BLOCKS, 256>>>(out);                  // 5472 blocks
}